// round 13
// baseline (speedup 1.0000x reference)
#include <cuda_runtime.h>
#include <cuda_bf16.h>
#include <math.h>
#include <float.h>
#include <stdint.h>

#define B_    4
#define NIN_  4096
#define M_    16384
#define CIN_  256
#define COUT_ 128
#define NSEG_ 4
#define SEGC_ (NIN_ / NSEG_)

#define KPAD  40

typedef unsigned long long ull;
typedef unsigned int u32;

// ---------------- f32x2 packed helpers ----------------
__device__ __forceinline__ ull pack2(float lo, float hi) {
    ull r; asm("mov.b64 %0,{%1,%2};" : "=l"(r) : "f"(lo), "f"(hi)); return r;
}
__device__ __forceinline__ void unpack2(float& lo, float& hi, ull v) {
    asm("mov.b64 {%0,%1},%2;" : "=f"(lo), "=f"(hi) : "l"(v));
}
__device__ __forceinline__ ull fma2(ull a, ull b, ull c) {
    ull d; asm("fma.rn.f32x2 %0,%1,%2,%3;" : "=l"(d) : "l"(a), "l"(b), "l"(c)); return d;
}
__device__ __forceinline__ ull mul2(ull a, ull b) {
    ull d; asm("mul.rn.f32x2 %0,%1,%2;" : "=l"(d) : "l"(a), "l"(b)); return d;
}
__device__ __forceinline__ ull add2(ull a, ull b) {
    ull d; asm("add.rn.f32x2 %0,%1,%2;" : "=l"(d) : "l"(a), "l"(b)); return d;
}

#define MMA16816(C, A, Bf)                                                   \
    asm volatile(                                                            \
        "mma.sync.aligned.m16n8k16.row.col.f32.bf16.bf16.f32 "               \
        "{%0,%1,%2,%3},{%4,%5,%6,%7},{%8,%9},{%0,%1,%2,%3};"                 \
        : "+f"((C)[0]), "+f"((C)[1]), "+f"((C)[2]), "+f"((C)[3])             \
        : "r"((A)[0]), "r"((A)[1]), "r"((A)[2]), "r"((A)[3]),                \
          "r"((Bf)[0]), "r"((Bf)[1]))

__device__ __forceinline__ u32 split_pack_hi(float a, float b,
                                             __nv_bfloat16& ha, __nv_bfloat16& hb) {
    ha = __float2bfloat16(a);
    hb = __float2bfloat16(b);
    return (u32)__bfloat16_as_ushort(ha) | ((u32)__bfloat16_as_ushort(hb) << 16);
}
__device__ __forceinline__ u32 pack_lo(float a, float b,
                                       __nv_bfloat16 ha, __nv_bfloat16 hb) {
    __nv_bfloat16 la = __float2bfloat16(a - __bfloat162float(ha));
    __nv_bfloat16 lb = __float2bfloat16(b - __bfloat162float(hb));
    return (u32)__bfloat16_as_ushort(la) | ((u32)__bfloat16_as_ushort(lb) << 16);
}

// ---------------- scratch ----------------
__device__ float g_act1[B_ * NIN_ * COUT_];
__device__ float g_act2[B_ * NIN_ * COUT_];
__device__ float g_featT[B_ * NIN_ * COUT_];
__device__ float g_pval[B_ * NSEG_ * M_ * 3];
__device__ int   g_pidx[B_ * NSEG_ * M_ * 3];
__device__ __nv_bfloat16 g_w1hi[COUT_ * CIN_],  g_w1lo[COUT_ * CIN_];
__device__ __nv_bfloat16 g_w2hi[COUT_ * COUT_], g_w2lo[COUT_ * COUT_];
__device__ __nv_bfloat16 g_w3hi[COUT_ * COUT_], g_w3lo[COUT_ * COUT_];

// ---------------- W fp32 -> bf16 hi/lo pre-split (once per layer) ----------------
__global__ __launch_bounds__(256) void wsplit_kernel(
    const float* __restrict__ src, __nv_bfloat16* __restrict__ hi,
    __nv_bfloat16* __restrict__ lo, int n)
{
    int i = blockIdx.x * 256 + threadIdx.x;
    if (i < n) {
        float v = src[i];
        __nv_bfloat16 h = __float2bfloat16(v);
        hi[i] = h;
        lo[i] = __float2bfloat16(v - __bfloat162float(h));
    }
}

// ---------------- tensor-core MLP layer (reg-prefetch pipelined) ----------------
// Y[n][cout] = relu(sc*sum_k W[cout,k] X[k,n] + shf); W pre-split bf16 hi/lo.
// xmode 0: X fp32 [n][k]; xmode 1: X fp32 [k][n] (rgb).
__global__ __launch_bounds__(256) void mlp_mma_kernel(
    const float* __restrict__ X,
    const __nv_bfloat16* __restrict__ Whi, const __nv_bfloat16* __restrict__ Wlo,
    const float* __restrict__ bias, const float* __restrict__ gamma,
    const float* __restrict__ betap, const float* __restrict__ rmean,
    const float* __restrict__ rvar,
    float* __restrict__ Y, int K, int xmode)
{
    __shared__ __nv_bfloat16 WsH[COUT_][KPAD];
    __shared__ __nv_bfloat16 WsL[COUT_][KPAD];
    __shared__ __nv_bfloat16 XsH[64][KPAD];
    __shared__ __nv_bfloat16 XsL[64][KPAD];
    __shared__ float s_sc[COUT_], s_sh[COUT_];

    const int tid  = threadIdx.x;
    const int b    = blockIdx.y;
    const int n0   = blockIdx.x * 64;
    const int wid  = tid >> 5, lane = tid & 31;
    const int wm   = wid >> 1, wn = wid & 1;
    const int g    = lane >> 2, tig = lane & 3;

    if (tid < COUT_) {
        float s = gamma[tid] / sqrtf(rvar[tid] + 1e-5f);
        s_sc[tid] = s;
        s_sh[tid] = betap[tid] + (bias[tid] - rmean[tid]) * s;
    }

    float acc[2][4][4];
#pragma unroll
    for (int ma = 0; ma < 2; ma++)
#pragma unroll
        for (int na = 0; na < 4; na++)
#pragma unroll
            for (int r = 0; r < 4; r++) acc[ma][na][r] = 0.f;

    const float* Xb = X + (size_t)b * K * NIN_;

    // per-thread staging coordinates
    // W: 8 u32 per split (128 rows x 16 u32)
    int wrow[8], wcp[8];
#pragma unroll
    for (int l = 0; l < 8; l++) { int idx = tid + l * 256; wrow[l] = idx >> 4; wcp[l] = idx & 15; }
    // X mode0: 4 float2 (64 rows x 16 pairs); mode1: 8 scalars (32k x 64n)
    int xrow[4], xcp[4], xkk[8], xnn[8];
#pragma unroll
    for (int l = 0; l < 4; l++) { int idx = tid + l * 256; xrow[l] = idx >> 4; xcp[l] = idx & 15; }
#pragma unroll
    for (int l = 0; l < 8; l++) { int idx = tid + l * 256; xkk[l] = idx >> 6; xnn[l] = idx & 63; }

    u32 wh[8], wl[8];
    float2 xf[4];
    float  xsc[8];

    // prefetch tile 0
#pragma unroll
    for (int l = 0; l < 8; l++) {
        wh[l] = *((const u32*)(Whi + (size_t)wrow[l] * K) + wcp[l]);
        wl[l] = *((const u32*)(Wlo + (size_t)wrow[l] * K) + wcp[l]);
    }
    if (xmode == 0) {
#pragma unroll
        for (int l = 0; l < 4; l++)
            xf[l] = *(const float2*)(Xb + (size_t)(n0 + xrow[l]) * K + 2 * xcp[l]);
    } else {
#pragma unroll
        for (int l = 0; l < 8; l++)
            xsc[l] = Xb[(size_t)xkk[l] * NIN_ + n0 + xnn[l]];
    }

    const int T = K >> 5;
    for (int t = 0; t < T; t++) {
        __syncthreads();   // previous tile's mma done; smem safe to overwrite
        // store staged tile (X converts in-register)
#pragma unroll
        for (int l = 0; l < 8; l++) {
            *(u32*)&WsH[wrow[l]][2 * wcp[l]] = wh[l];
            *(u32*)&WsL[wrow[l]][2 * wcp[l]] = wl[l];
        }
        if (xmode == 0) {
#pragma unroll
            for (int l = 0; l < 4; l++) {
                __nv_bfloat16 h0, h1;
                *(u32*)&XsH[xrow[l]][2 * xcp[l]] = split_pack_hi(xf[l].x, xf[l].y, h0, h1);
                *(u32*)&XsL[xrow[l]][2 * xcp[l]] = pack_lo(xf[l].x, xf[l].y, h0, h1);
            }
        } else {
#pragma unroll
            for (int l = 0; l < 8; l++) {
                __nv_bfloat16 h = __float2bfloat16(xsc[l]);
                XsH[xnn[l]][xkk[l]] = h;
                XsL[xnn[l]][xkk[l]] = __float2bfloat16(xsc[l] - __bfloat162float(h));
            }
        }
        __syncthreads();

        // prefetch next tile into registers (overlaps mma below)
        if (t + 1 < T) {
            int k0 = (t + 1) * 32;
#pragma unroll
            for (int l = 0; l < 8; l++) {
                wh[l] = *((const u32*)(Whi + (size_t)wrow[l] * K + k0) + wcp[l]);
                wl[l] = *((const u32*)(Wlo + (size_t)wrow[l] * K + k0) + wcp[l]);
            }
            if (xmode == 0) {
#pragma unroll
                for (int l = 0; l < 4; l++)
                    xf[l] = *(const float2*)(Xb + (size_t)(n0 + xrow[l]) * K + k0 + 2 * xcp[l]);
            } else {
#pragma unroll
                for (int l = 0; l < 8; l++)
                    xsc[l] = Xb[(size_t)(k0 + xkk[l]) * NIN_ + n0 + xnn[l]];
            }
        }

#pragma unroll
        for (int ks = 0; ks < 2; ks++) {
            const int k16 = ks * 16;
            u32 aH[2][4], aL[2][4], bH[4][2], bL[4][2];
#pragma unroll
            for (int ma = 0; ma < 2; ma++) {
                int r0 = wm * 32 + ma * 16;
                aH[ma][0] = *(const u32*)&WsH[r0 + g][k16 + 2 * tig];
                aH[ma][1] = *(const u32*)&WsH[r0 + g + 8][k16 + 2 * tig];
                aH[ma][2] = *(const u32*)&WsH[r0 + g][k16 + 2 * tig + 8];
                aH[ma][3] = *(const u32*)&WsH[r0 + g + 8][k16 + 2 * tig + 8];
                aL[ma][0] = *(const u32*)&WsL[r0 + g][k16 + 2 * tig];
                aL[ma][1] = *(const u32*)&WsL[r0 + g + 8][k16 + 2 * tig];
                aL[ma][2] = *(const u32*)&WsL[r0 + g][k16 + 2 * tig + 8];
                aL[ma][3] = *(const u32*)&WsL[r0 + g + 8][k16 + 2 * tig + 8];
            }
#pragma unroll
            for (int na = 0; na < 4; na++) {
                int nb = wn * 32 + na * 8 + g;
                bH[na][0] = *(const u32*)&XsH[nb][k16 + 2 * tig];
                bH[na][1] = *(const u32*)&XsH[nb][k16 + 2 * tig + 8];
                bL[na][0] = *(const u32*)&XsL[nb][k16 + 2 * tig];
                bL[na][1] = *(const u32*)&XsL[nb][k16 + 2 * tig + 8];
            }
#pragma unroll
            for (int ma = 0; ma < 2; ma++)
#pragma unroll
                for (int na = 0; na < 4; na++) {
                    MMA16816(acc[ma][na], aH[ma], bH[na]);
                    MMA16816(acc[ma][na], aH[ma], bL[na]);
                    MMA16816(acc[ma][na], aL[ma], bH[na]);
                }
        }
    }

    // epilogue: BN + ReLU, write fp32 [n][cout]
    float* base = Y + (size_t)b * NIN_ * COUT_;
#pragma unroll
    for (int ma = 0; ma < 2; ma++) {
        int r0 = wm * 32 + ma * 16 + g;
        int r1 = r0 + 8;
        float sc0 = s_sc[r0], sh0 = s_sh[r0];
        float sc1 = s_sc[r1], sh1 = s_sh[r1];
#pragma unroll
        for (int na = 0; na < 4; na++) {
            int n = n0 + wn * 32 + na * 8 + 2 * tig;
            base[(size_t)(n)     * COUT_ + r0] = fmaxf(__fmaf_rn(acc[ma][na][0], sc0, sh0), 0.f);
            base[(size_t)(n + 1) * COUT_ + r0] = fmaxf(__fmaf_rn(acc[ma][na][1], sc0, sh0), 0.f);
            base[(size_t)(n)     * COUT_ + r1] = fmaxf(__fmaf_rn(acc[ma][na][2], sc1, sh1), 0.f);
            base[(size_t)(n + 1) * COUT_ + r1] = fmaxf(__fmaf_rn(acc[ma][na][3], sc1, sh1), 0.f);
        }
    }
}

// ---------------- segmented exact top-3 scan (proven R9 version) ----------------
#define INSERT3(d_, j_, s0_, s1_, s2_, i0_, i1_, i2_)                      \
    if (d_ < s2_) {                                                        \
        if (d_ < s1_) {                                                    \
            s2_ = s1_; i2_ = i1_;                                          \
            if (d_ < s0_) { s1_ = s0_; i1_ = i0_; s0_ = d_; i0_ = j_; }    \
            else          { s1_ = d_;  i1_ = j_; }                         \
        } else { s2_ = d_; i2_ = j_; }                                     \
    }

__global__ __launch_bounds__(256) void scan_kernel(
    const float* __restrict__ xyzin, const float* __restrict__ xyzout,
    float* __restrict__ pval, int* __restrict__ pidx)
{
    __shared__ __align__(16) float xs[SEGC_];
    __shared__ __align__(16) float ys[SEGC_];
    __shared__ __align__(16) float zs[SEGC_];
    __shared__ __align__(16) float ss[SEGC_];

    const int tid = threadIdx.x;
    const int seg = blockIdx.y;
    const int b   = blockIdx.z;
    const int jbase = seg * SEGC_;
    const float* pin = xyzin + ((size_t)b * NIN_ + jbase) * 3;

    for (int j = tid; j < SEGC_; j += 256) {
        float x = pin[j * 3 + 0];
        float y = pin[j * 3 + 1];
        float z = pin[j * 3 + 2];
        xs[j] = x; ys[j] = y; zs[j] = z;
        ss[j] = __fadd_rn(__fadd_rn(__fmul_rn(x, x), __fmul_rn(y, y)),
                          __fmul_rn(z, z));
    }
    __syncthreads();

    const int m0 = blockIdx.x * 512 + tid;
    const int m1 = m0 + 256;

    const float* q0 = xyzout + ((size_t)b * M_ + m0) * 3;
    const float* q1 = xyzout + ((size_t)b * M_ + m1) * 3;
    float q0x = q0[0], q0y = q0[1], q0z = q0[2];
    float q1x = q1[0], q1y = q1[1], q1z = q1[2];
    float q0n = __fadd_rn(__fadd_rn(__fmul_rn(q0x, q0x), __fmul_rn(q0y, q0y)),
                          __fmul_rn(q0z, q0z));
    float q1n = __fadd_rn(__fadd_rn(__fmul_rn(q1x, q1x), __fmul_rn(q1y, q1y)),
                          __fmul_rn(q1z, q1z));

    const ull qx20 = pack2(q0x, q0x), qy20 = pack2(q0y, q0y);
    const ull qz20 = pack2(q0z, q0z), qn20 = pack2(q0n, q0n);
    const ull qx21 = pack2(q1x, q1x), qy21 = pack2(q1y, q1y);
    const ull qz21 = pack2(q1z, q1z), qn21 = pack2(q1n, q1n);
    const ull n22  = pack2(-2.0f, -2.0f);

    float a_s0 = FLT_MAX, a_s1 = FLT_MAX, a_s2 = FLT_MAX;
    float b_s0 = FLT_MAX, b_s1 = FLT_MAX, b_s2 = FLT_MAX;
    int a_i0 = 0, a_i1 = 0, a_i2 = 0;
    int b_i0 = 0, b_i1 = 0, b_i2 = 0;

    const ulonglong2* xs4 = (const ulonglong2*)xs;
    const ulonglong2* ys4 = (const ulonglong2*)ys;
    const ulonglong2* zs4 = (const ulonglong2*)zs;
    const ulonglong2* ss4 = (const ulonglong2*)ss;

#pragma unroll 2
    for (int jq = 0; jq < SEGC_ / 4; jq++) {
        ulonglong2 xq = xs4[jq], yq = ys4[jq], zq = zs4[jq], sq = ss4[jq];
#pragma unroll
        for (int p = 0; p < 2; p++) {
            ull xp = p ? xq.y : xq.x;
            ull yp = p ? yq.y : yq.x;
            ull zp = p ? zq.y : zq.x;
            ull sp = p ? sq.y : sq.x;
            int j = jbase + 4 * jq + 2 * p;
            {
                ull dot = fma2(qz20, zp, fma2(qy20, yp, mul2(qx20, xp)));
                ull d2  = fma2(n22, dot, add2(qn20, sp));
                float dlo, dhi; unpack2(dlo, dhi, d2);
                if (__builtin_expect(fminf(dlo, dhi) < a_s2, 0)) {
                    float cl = (dlo < 0.0f) ? 1e-7f : dlo;
                    float ch = (dhi < 0.0f) ? 1e-7f : dhi;
                    INSERT3(cl, j,     a_s0, a_s1, a_s2, a_i0, a_i1, a_i2);
                    INSERT3(ch, j + 1, a_s0, a_s1, a_s2, a_i0, a_i1, a_i2);
                }
            }
            {
                ull dot = fma2(qz21, zp, fma2(qy21, yp, mul2(qx21, xp)));
                ull d2  = fma2(n22, dot, add2(qn21, sp));
                float dlo, dhi; unpack2(dlo, dhi, d2);
                if (__builtin_expect(fminf(dlo, dhi) < b_s2, 0)) {
                    float cl = (dlo < 0.0f) ? 1e-7f : dlo;
                    float ch = (dhi < 0.0f) ? 1e-7f : dhi;
                    INSERT3(cl, j,     b_s0, b_s1, b_s2, b_i0, b_i1, b_i2);
                    INSERT3(ch, j + 1, b_s0, b_s1, b_s2, b_i0, b_i1, b_i2);
                }
            }
        }
    }

    {
        size_t o = (((size_t)b * NSEG_ + seg) * M_ + m0) * 3;
        pval[o + 0] = a_s0; pval[o + 1] = a_s1; pval[o + 2] = a_s2;
        pidx[o + 0] = a_i0; pidx[o + 1] = a_i1; pidx[o + 2] = a_i2;
    }
    {
        size_t o = (((size_t)b * NSEG_ + seg) * M_ + m1) * 3;
        pval[o + 0] = b_s0; pval[o + 1] = b_s1; pval[o + 2] = b_s2;
        pidx[o + 0] = b_i0; pidx[o + 1] = b_i1; pidx[o + 2] = b_i2;
    }
}

// ---------------- fused merge + gather + weighted interpolation ----------------
__global__ __launch_bounds__(128) void interp_kernel(
    const float* __restrict__ featT,
    const float* __restrict__ pval, const int* __restrict__ pidx,
    float* __restrict__ out)
{
    __shared__ float sacc[64][COUT_ + 1];
    __shared__ float sw[64 * 3];
    __shared__ int   si[64 * 3];
    const int tid = threadIdx.x;
    const int b   = blockIdx.y;
    const int m0  = blockIdx.x * 64;

    if (tid < 64) {
        const int m = m0 + tid;
        float v[NSEG_ * 3];
        int   ix[NSEG_ * 3];
#pragma unroll
        for (int s = 0; s < NSEG_; s++) {
            size_t o = (((size_t)b * NSEG_ + s) * M_ + m) * 3;
#pragma unroll
            for (int k = 0; k < 3; k++) {
                v[s * 3 + k]  = pval[o + k];
                ix[s * 3 + k] = pidx[o + k];
            }
        }
        float rs[3]; int ri[3];
#pragma unroll
        for (int k = 0; k < 3; k++) {
            int best = 0;
#pragma unroll
            for (int t = 1; t < NSEG_ * 3; t++) {
                bool better = (v[t] < v[best]) ||
                              (v[t] == v[best] && ix[t] < ix[best]);
                if (better) best = t;
            }
            rs[k] = v[best]; ri[k] = ix[best];
            v[best] = FLT_MAX; ix[best] = 0x7FFFFFFF;
        }
        float w0 = __fdiv_rn(1.0f, rs[0]);
        float w1 = __fdiv_rn(1.0f, rs[1]);
        float w2 = __fdiv_rn(1.0f, rs[2]);
        float wsum = __fadd_rn(__fadd_rn(w0, w1), w2);
        sw[tid * 3 + 0] = __fdiv_rn(w0, wsum);
        sw[tid * 3 + 1] = __fdiv_rn(w1, wsum);
        sw[tid * 3 + 2] = __fdiv_rn(w2, wsum);
        si[tid * 3 + 0] = ri[0];
        si[tid * 3 + 1] = ri[1];
        si[tid * 3 + 2] = ri[2];
    }
    __syncthreads();

    const float* fb = featT + (size_t)b * NIN_ * COUT_;
    const int c = tid;
#pragma unroll 2
    for (int qq = 0; qq < 64; qq++) {
        float w0 = sw[qq * 3], w1 = sw[qq * 3 + 1], w2 = sw[qq * 3 + 2];
        const float* f0 = fb + (size_t)si[qq * 3]     * COUT_;
        const float* f1 = fb + (size_t)si[qq * 3 + 1] * COUT_;
        const float* f2 = fb + (size_t)si[qq * 3 + 2] * COUT_;
        sacc[qq][c] = __fmaf_rn(w2, f2[c],
                      __fmaf_rn(w1, f1[c], __fmul_rn(w0, f0[c])));
    }
    __syncthreads();

#pragma unroll
    for (int cc = 0; cc < COUT_; cc += 2) {
        int ci = cc + (tid >> 6);
        int mi = tid & 63;
        out[((size_t)b * COUT_ + ci) * M_ + m0 + mi] = sacc[mi][ci];
    }
}

// ---------------- launch (stream-forked: scan || wsplit+MLP chain) ----------------
extern "C" void kernel_launch(void* const* d_in, const int* in_sizes, int n_in,
                              void* d_out, int out_size)
{
    (void)in_sizes; (void)n_in; (void)out_size;
    const float* rgb    = (const float*)d_in[0];
    const float* xyzin  = (const float*)d_in[1];
    const float* xyzout = (const float*)d_in[2];
    const float* w1 = (const float*)d_in[3];
    const float* b1 = (const float*)d_in[4];
    const float* g1 = (const float*)d_in[5];
    const float* be1 = (const float*)d_in[6];
    const float* rm1 = (const float*)d_in[7];
    const float* rv1 = (const float*)d_in[8];
    const float* w2 = (const float*)d_in[9];
    const float* b2 = (const float*)d_in[10];
    const float* g2 = (const float*)d_in[11];
    const float* be2 = (const float*)d_in[12];
    const float* rm2 = (const float*)d_in[13];
    const float* rv2 = (const float*)d_in[14];
    const float* w3 = (const float*)d_in[15];
    const float* b3 = (const float*)d_in[16];
    const float* g3 = (const float*)d_in[17];
    const float* be3 = (const float*)d_in[18];
    const float* rm3 = (const float*)d_in[19];
    const float* rv3 = (const float*)d_in[20];
    float* out = (float*)d_out;

    float *act1, *act2, *featT, *pvp;
    int *pip;
    __nv_bfloat16 *w1hi, *w1lo, *w2hi, *w2lo, *w3hi, *w3lo;
    cudaGetSymbolAddress((void**)&act1,  g_act1);
    cudaGetSymbolAddress((void**)&act2,  g_act2);
    cudaGetSymbolAddress((void**)&featT, g_featT);
    cudaGetSymbolAddress((void**)&pvp,   g_pval);
    cudaGetSymbolAddress((void**)&pip,   g_pidx);
    cudaGetSymbolAddress((void**)&w1hi,  g_w1hi);
    cudaGetSymbolAddress((void**)&w1lo,  g_w1lo);
    cudaGetSymbolAddress((void**)&w2hi,  g_w2hi);
    cudaGetSymbolAddress((void**)&w2lo,  g_w2lo);
    cudaGetSymbolAddress((void**)&w3hi,  g_w3hi);
    cudaGetSymbolAddress((void**)&w3lo,  g_w3lo);

    static cudaStream_t s_side = nullptr;
    static cudaEvent_t  ev_fork = nullptr, ev_join = nullptr;
    if (s_side == nullptr) {
        cudaStreamCreateWithFlags(&s_side, cudaStreamNonBlocking);
        cudaEventCreateWithFlags(&ev_fork, cudaEventDisableTiming);
        cudaEventCreateWithFlags(&ev_join, cudaEventDisableTiming);
    }

    cudaEventRecord(ev_fork, 0);
    cudaStreamWaitEvent(s_side, ev_fork, 0);

    // side stream: 3-NN scan (unchanged)
    dim3 scan_grid(M_ / 512, NSEG_, B_);
    scan_kernel<<<scan_grid, 256, 0, s_side>>>(xyzin, xyzout, pvp, pip);
    cudaEventRecord(ev_join, s_side);

    // default stream: W pre-splits + pipelined tensor-core MLP chain
    wsplit_kernel<<<(COUT_ * CIN_ + 255) / 256, 256>>>(w1, w1hi, w1lo, COUT_ * CIN_);
    wsplit_kernel<<<(COUT_ * COUT_ + 255) / 256, 256>>>(w2, w2hi, w2lo, COUT_ * COUT_);
    wsplit_kernel<<<(COUT_ * COUT_ + 255) / 256, 256>>>(w3, w3hi, w3lo, COUT_ * COUT_);

    dim3 gemm_grid(NIN_ / 64, B_);
    mlp_mma_kernel<<<gemm_grid, 256>>>(rgb,  w1hi, w1lo, b1, g1, be1, rm1, rv1,
                                       act1,  CIN_,  1);
    mlp_mma_kernel<<<gemm_grid, 256>>>(act1, w2hi, w2lo, b2, g2, be2, rm2, rv2,
                                       act2,  COUT_, 0);
    mlp_mma_kernel<<<gemm_grid, 256>>>(act2, w3hi, w3lo, b3, g3, be3, rm3, rv3,
                                       featT, COUT_, 0);

    cudaStreamWaitEvent(0, ev_join, 0);

    dim3 interp_grid(M_ / 64, B_);
    interp_kernel<<<interp_grid, 128>>>(featT, pvp, pip, out);
}